// round 1
// baseline (speedup 1.0000x reference)
#include <cuda_runtime.h>

#define NN 8192
#define FF 256
typedef unsigned long long ull;

// Scratch (static device globals — no allocation allowed)
__device__ float g_Wh[NN * FF];   // 8 MB
__device__ float g_s1[NN];
__device__ float g_s2[NN];
__device__ float g_M[NN];

// ---------------------------------------------------------------------------
// K1: Wh = h @ W   (8192x256 @ 256x256, fp32)
// 256 blocks x 256 threads; block handles 32 rows; k staged in chunks of 32.
// ---------------------------------------------------------------------------
__global__ void __launch_bounds__(256) k_wh(const float* __restrict__ h,
                                            const float* __restrict__ W) {
    __shared__ float Ws[32][256];   // 32 KB
    __shared__ float hs[32][32];    // 4 KB
    int t  = threadIdx.x;
    int r0 = blockIdx.x * 32;

    float acc[32];
#pragma unroll
    for (int r = 0; r < 32; r++) acc[r] = 0.f;

    for (int kc = 0; kc < 8; kc++) {
        __syncthreads();
        // W chunk: rows kc*32..+31, all 256 cols
#pragma unroll
        for (int kk = 0; kk < 32; kk++)
            Ws[kk][t] = W[(kc * 32 + kk) * FF + t];
        // h chunk: 32 rows x 32 k (float4 per thread)
        {
            int r = t >> 3, c4 = (t & 7) * 4;
            float4 v = *(const float4*)&h[(r0 + r) * FF + kc * 32 + c4];
            hs[r][c4 + 0] = v.x; hs[r][c4 + 1] = v.y;
            hs[r][c4 + 2] = v.z; hs[r][c4 + 3] = v.w;
        }
        __syncthreads();
#pragma unroll
        for (int kk = 0; kk < 32; kk++) {
            float w = Ws[kk][t];
#pragma unroll
            for (int r = 0; r < 32; r++)
                acc[r] = fmaf(hs[r][kk], w, acc[r]);   // hs broadcast, conflict-free
        }
    }
#pragma unroll
    for (int r = 0; r < 32; r++)
        g_Wh[(r0 + r) * FF + t] = acc[r];
}

// ---------------------------------------------------------------------------
// K1b: s1 = Wh @ a1, s2 = Wh @ a2.  One warp per row.
// ---------------------------------------------------------------------------
__global__ void __launch_bounds__(256) k_s12(const float* __restrict__ a) {
    int warp = threadIdx.x >> 5, lane = threadIdx.x & 31;
    int r = blockIdx.x * 8 + warp;
    const float4* wh = (const float4*)&g_Wh[r * FF];
    float v1 = 0.f, v2 = 0.f;
#pragma unroll
    for (int i = 0; i < 2; i++) {
        int k4 = lane + i * 32;                 // float4 index; k = k4*4
        float4 w  = wh[k4];
        float4 a1 = *(const float4*)&a[k4 * 4];
        float4 a2 = *(const float4*)&a[FF + k4 * 4];
        v1 += w.x * a1.x + w.y * a1.y + w.z * a1.z + w.w * a1.w;
        v2 += w.x * a2.x + w.y * a2.y + w.z * a2.z + w.w * a2.w;
    }
#pragma unroll
    for (int o = 16; o; o >>= 1) {
        v1 += __shfl_down_sync(~0u, v1, o);
        v2 += __shfl_down_sync(~0u, v2, o);
    }
    if (lane == 0) { g_s1[r] = v1; g_s2[r] = v2; }
}

// ---------------------------------------------------------------------------
// K2: M_i = max_{j: adj_ij=1} s2_j  (lrelu monotone => row max of e derivable)
// One block per row; int4/float4 coalesced streaming of the adj row.
// ---------------------------------------------------------------------------
__global__ void __launch_bounds__(256) k_rowmax(const int* __restrict__ adj) {
    int t = threadIdx.x;
    int row = blockIdx.x;
    const int4*   arow = (const int4*)&adj[(long long)row * NN];
    const float4* s2v  = (const float4*)g_s2;
    float m = -3.4e38f;
#pragma unroll
    for (int i = 0; i < 8; i++) {
        int idx = i * 256 + t;
        int4   A = arow[idx];
        float4 S = s2v[idx];
        if (A.x) m = fmaxf(m, S.x);
        if (A.y) m = fmaxf(m, S.y);
        if (A.z) m = fmaxf(m, S.z);
        if (A.w) m = fmaxf(m, S.w);
    }
#pragma unroll
    for (int o = 16; o; o >>= 1) m = fmaxf(m, __shfl_down_sync(~0u, m, o));
    __shared__ float sm[8];
    if ((t & 31) == 0) sm[t >> 5] = m;
    __syncthreads();
    if (t == 0) {
#pragma unroll
        for (int w = 1; w < 8; w++) m = fmaxf(m, sm[w]);
        g_M[row] = m;
    }
}

// ---------------------------------------------------------------------------
// K3: out_i = (sum_j p_ij Wh_j) / Z_i,  p_ij = adj_ij ? exp(lrelu(s1_i+s2_j)-m_i) : 0
// 256 blocks x 256 threads; block = 32 rows; j streamed in tiles of 32.
// Accumulators as 16 row-pair f32x2 register pairs per thread (1 column each).
// ---------------------------------------------------------------------------
__global__ void __launch_bounds__(256) k_attn(const int* __restrict__ adj,
                                              float* __restrict__ out) {
    __shared__ float  Whs[32][256];   // 32 KB
    __shared__ int    adjs[32][33];   // padded: conflict-free r-varying reads
    __shared__ float2 ps[32][16];     // [j][row-pair] -> broadcast LDS.64
    __shared__ float  s2t[32];
    __shared__ float  s1s[32], ms[32], zinv[32];

    int t  = threadIdx.x;
    int r0 = blockIdx.x * 32;

    if (t < 32) {
        float s1v = g_s1[r0 + t];
        s1s[t] = s1v;
        float x = s1v + g_M[r0 + t];
        ms[t] = fmaxf(x, 0.2f * x);    // lrelu
    }

    ull acc[16];
#pragma unroll
    for (int i = 0; i < 16; i++) acc[i] = 0ull;
    float zx = 0.f, zy = 0.f;          // live only in threads t < 16

    for (int jt = 0; jt < NN; jt += 32) {
        __syncthreads();
        // adj tile (coalesced int4 per 8-thread row group)
        {
            int r = t >> 3, c4 = (t & 7) * 4;
            int4 A = *(const int4*)&adj[(long long)(r0 + r) * NN + jt + c4];
            adjs[r][c4 + 0] = A.x; adjs[r][c4 + 1] = A.y;
            adjs[r][c4 + 2] = A.z; adjs[r][c4 + 3] = A.w;
        }
        // Wh tile
#pragma unroll
        for (int jj = 0; jj < 32; jj++)
            Whs[jj][t] = g_Wh[(jt + jj) * FF + t];
        if (t < 32) s2t[t] = g_s2[jt + t];
        __syncthreads();

        // p tile: each thread fills 2 float2 (row-pair) entries
#pragma unroll
        for (int u = 0; u < 2; u++) {
            int lin = t * 2 + u;
            int j = lin >> 4, rp = lin & 15;
            int ra = rp * 2, rb = rp * 2 + 1;
            float xa = s1s[ra] + s2t[j];
            float xb = s1s[rb] + s2t[j];
            float ea = fmaxf(xa, 0.2f * xa);
            float eb = fmaxf(xb, 0.2f * xb);
            float pa = adjs[ra][j] ? __expf(ea - ms[ra]) : 0.f;
            float pb = adjs[rb][j] ? __expf(eb - ms[rb]) : 0.f;
            ps[j][rp] = make_float2(pa, pb);
        }
        __syncthreads();

        // Z accumulation (threads 0..15, one row-pair each; register-resident)
        if (t < 16) {
            float sx = 0.f, sy = 0.f;
#pragma unroll
            for (int j = 0; j < 32; j++) { float2 p = ps[j][t]; sx += p.x; sy += p.y; }
            zx += sx; zy += sy;
        }

        // Main accumulate: packed dual-fp32 FMA (f32x2), p row-pairs broadcast
        const ull* ps64 = (const ull*)ps;
#pragma unroll 4
        for (int j = 0; j < 32; j++) {
            float w = Whs[j][t];
            ull w2;
            asm("mov.b64 %0, {%1, %1};" : "=l"(w2) : "f"(w));
#pragma unroll
            for (int rp = 0; rp < 16; rp++) {
                ull p2 = ps64[j * 16 + rp];
                asm("fma.rn.f32x2 %0, %1, %2, %0;" : "+l"(acc[rp]) : "l"(p2), "l"(w2));
            }
        }
    }

    __syncthreads();
    if (t < 16) {
        zinv[2 * t]     = __frcp_rn(zx);
        zinv[2 * t + 1] = __frcp_rn(zy);
    }
    __syncthreads();

#pragma unroll
    for (int rp = 0; rp < 16; rp++) {
        float lo, hi;
        asm("mov.b64 {%0, %1}, %2;" : "=f"(lo), "=f"(hi) : "l"(acc[rp]));
        out[(r0 + 2 * rp) * FF + t]     = lo * zinv[2 * rp];
        out[(r0 + 2 * rp + 1) * FF + t] = hi * zinv[2 * rp + 1];
    }
}

// ---------------------------------------------------------------------------
// Inputs (metadata order): h [8192*256 f32], adj [8192*8192 i32],
//                          W [256*256 f32], a [512 f32].  Output: f32 8192*256.
// ---------------------------------------------------------------------------
extern "C" void kernel_launch(void* const* d_in, const int* in_sizes, int n_in,
                              void* d_out, int out_size) {
    const float* h   = (const float*)d_in[0];
    const int*   adj = (const int*)d_in[1];
    const float* W   = (const float*)d_in[2];
    const float* a   = (const float*)d_in[3];
    float* out = (float*)d_out;

    k_wh<<<256, 256>>>(h, W);
    k_s12<<<1024, 256>>>(a);
    k_rowmax<<<8192, 256>>>(adj);
    k_attn<<<256, 256>>>(adj, out);
}

// round 2
// speedup vs baseline: 1.4262x; 1.4262x over previous
#include <cuda_runtime.h>

#define NN 8192
#define FF 256
typedef unsigned long long ull;

// Scratch (static device globals — no allocation allowed)
__device__ float g_Wh[NN * FF];   // 8 MB
__device__ float g_E1[NN];        // exp(s1)
__device__ float g_B1[NN];        // exp(0.2*s1)
__device__ float g_E2[NN];        // exp(s2)
__device__ float g_F2[NN];        // exp(0.2*s2)

// ---------------------------------------------------------------------------
// K1: Wh = h @ W   (8192x256 @ 256x256, fp32)
// ---------------------------------------------------------------------------
__global__ void __launch_bounds__(256) k_wh(const float* __restrict__ h,
                                            const float* __restrict__ W) {
    __shared__ float Ws[32][256];
    __shared__ float hs[32][32];
    int t  = threadIdx.x;
    int r0 = blockIdx.x * 32;

    float acc[32];
#pragma unroll
    for (int r = 0; r < 32; r++) acc[r] = 0.f;

    for (int kc = 0; kc < 8; kc++) {
        __syncthreads();
#pragma unroll
        for (int kk = 0; kk < 32; kk++)
            Ws[kk][t] = W[(kc * 32 + kk) * FF + t];
        {
            int r = t >> 3, c4 = (t & 7) * 4;
            float4 v = *(const float4*)&h[(r0 + r) * FF + kc * 32 + c4];
            hs[r][c4 + 0] = v.x; hs[r][c4 + 1] = v.y;
            hs[r][c4 + 2] = v.z; hs[r][c4 + 3] = v.w;
        }
        __syncthreads();
#pragma unroll
        for (int kk = 0; kk < 32; kk++) {
            float w = Ws[kk][t];
#pragma unroll
            for (int r = 0; r < 32; r++)
                acc[r] = fmaf(hs[r][kk], w, acc[r]);
        }
    }
#pragma unroll
    for (int r = 0; r < 32; r++)
        g_Wh[(r0 + r) * FF + t] = acc[r];
}

// ---------------------------------------------------------------------------
// K1b: s1 = Wh@a1, s2 = Wh@a2; store exp factors.
// exp(lrelu(s1_i+s2_j)) = max(E1_i*E2_j, B1_i*F2_j)   (exp monotone)
// No row-max subtraction needed: |s1+s2| <~ 8 -> exp in [3e-4, 3e3], fp32-safe.
// ---------------------------------------------------------------------------
__global__ void __launch_bounds__(256) k_s12(const float* __restrict__ a) {
    int warp = threadIdx.x >> 5, lane = threadIdx.x & 31;
    int r = blockIdx.x * 8 + warp;
    const float4* wh = (const float4*)&g_Wh[r * FF];
    float v1 = 0.f, v2 = 0.f;
#pragma unroll
    for (int i = 0; i < 2; i++) {
        int k4 = lane + i * 32;
        float4 w  = wh[k4];
        float4 a1 = *(const float4*)&a[k4 * 4];
        float4 a2 = *(const float4*)&a[FF + k4 * 4];
        v1 += w.x * a1.x + w.y * a1.y + w.z * a1.z + w.w * a1.w;
        v2 += w.x * a2.x + w.y * a2.y + w.z * a2.z + w.w * a2.w;
    }
#pragma unroll
    for (int o = 16; o; o >>= 1) {
        v1 += __shfl_down_sync(~0u, v1, o);
        v2 += __shfl_down_sync(~0u, v2, o);
    }
    if (lane == 0) {
        g_E1[r] = __expf(v1);
        g_B1[r] = __expf(0.2f * v1);
        g_E2[r] = __expf(v2);
        g_F2[r] = __expf(0.2f * v2);
    }
}

// ---------------------------------------------------------------------------
// K2: out_i = (sum_j p_ij Wh_j) / Z_i
//     p_ij = adj_ij ? max(E1_i*E2_j, B1_i*F2_j) : 0
// Block = 32 rows, 256 threads, 2 blocks/SM.
// Thread tile: 4 columns (cg) x 4 row-pairs (rg) -> 16 f32x2 accumulators.
// Per j: 4 LDS.64 (p pairs) + 1 LDS.128 (Wh) + 16 FFMA2  => FMA-pipe bound.
// ---------------------------------------------------------------------------
__global__ void __launch_bounds__(256, 2) k_attn(const int* __restrict__ adj,
                                                 float* __restrict__ out) {
    __shared__ float  Whs[32][256];   // 32 KB
    __shared__ float2 ps[32][17];     // [j][row-pair], padded (2-phase min)
    __shared__ float  A1s[32], B1s[32];
    __shared__ float  zinv[32];

    int t  = threadIdx.x;
    int r0 = blockIdx.x * 32;
    int cg = t >> 2;            // column group: cols cg*4 .. cg*4+3
    int rg = t & 3;             // row-pair group: rp = rg*4 .. rg*4+3
    int jj = t & 31;            // p-gen: j index within tile
    int w  = t >> 5;            // warp id: p-gen row-pairs 2w, 2w+1

    if (t < 32) { A1s[t] = g_E1[r0 + t]; B1s[t] = g_B1[r0 + t]; }

    ull acc[4][4];
#pragma unroll
    for (int k = 0; k < 4; k++)
#pragma unroll
        for (int c = 0; c < 4; c++) acc[k][c] = 0ull;
    float zr[4] = {0.f, 0.f, 0.f, 0.f};   // rows 4w..4w+3 (valid in all lanes)

    for (int jt = 0; jt < NN; jt += 32) {
        __syncthreads();   // previous tile's compute done before overwrite

        // ---- Wh tile fill: 2048 float4 / 256 threads = 8 each, coalesced
#pragma unroll
        for (int i = 0; i < 8; i++) {
            int f = i * 256 + t;
            int r = f >> 6, c4 = f & 63;
            *(float4*)&Whs[r][c4 * 4] =
                *(const float4*)&g_Wh[(jt + r) * FF + c4 * 4];
        }

        // ---- p tile + Z partial sums
        {
            float E2j = g_E2[jt + jj];
            float F2j = g_F2[jt + jj];
#pragma unroll
            for (int u = 0; u < 2; u++) {
                int rp = w * 2 + u;
                int ra = rp * 2, rb = rp * 2 + 1;
                int aA = adj[(long long)(r0 + ra) * NN + jt + jj];
                int aB = adj[(long long)(r0 + rb) * NN + jt + jj];
                float pa = aA ? fmaxf(A1s[ra] * E2j, B1s[ra] * F2j) : 0.f;
                float pb = aB ? fmaxf(A1s[rb] * E2j, B1s[rb] * F2j) : 0.f;
                ps[jj][rp] = make_float2(pa, pb);
                float sa = pa, sb = pb;
#pragma unroll
                for (int o = 16; o; o >>= 1) {
                    sa += __shfl_xor_sync(~0u, sa, o);
                    sb += __shfl_xor_sync(~0u, sb, o);
                }
                zr[2 * u]     += sa;
                zr[2 * u + 1] += sb;
            }
        }
        __syncthreads();

        // ---- main accumulate
#pragma unroll 8
        for (int j = 0; j < 32; j++) {
            float4 w4 = *(const float4*)&Whs[j][cg * 4];
            ull wd0, wd1, wd2, wd3;
            asm("mov.b64 %0, {%1, %1};" : "=l"(wd0) : "f"(w4.x));
            asm("mov.b64 %0, {%1, %1};" : "=l"(wd1) : "f"(w4.y));
            asm("mov.b64 %0, {%1, %1};" : "=l"(wd2) : "f"(w4.z));
            asm("mov.b64 %0, {%1, %1};" : "=l"(wd3) : "f"(w4.w));
#pragma unroll
            for (int k = 0; k < 4; k++) {
                ull p2 = *(const ull*)&ps[j][rg * 4 + k];
                asm("fma.rn.f32x2 %0, %1, %2, %0;" : "+l"(acc[k][0]) : "l"(p2), "l"(wd0));
                asm("fma.rn.f32x2 %0, %1, %2, %0;" : "+l"(acc[k][1]) : "l"(p2), "l"(wd1));
                asm("fma.rn.f32x2 %0, %1, %2, %0;" : "+l"(acc[k][2]) : "l"(p2), "l"(wd2));
                asm("fma.rn.f32x2 %0, %1, %2, %0;" : "+l"(acc[k][3]) : "l"(p2), "l"(wd3));
            }
        }
    }

    // ---- Z -> zinv (warp w owns rows 4w..4w+3; zr identical across lanes)
    if ((t & 31) == 0) {
#pragma unroll
        for (int k = 0; k < 4; k++) zinv[w * 4 + k] = __frcp_rn(zr[k]);
    }
    __syncthreads();

    // ---- epilogue: scale + store
#pragma unroll
    for (int k = 0; k < 4; k++) {
        int rowA = rg * 8 + 2 * k;
        int rowB = rowA + 1;
        float zA = zinv[rowA], zB = zinv[rowB];
        float lo0, hi0, lo1, hi1, lo2, hi2, lo3, hi3;
        asm("mov.b64 {%0, %1}, %2;" : "=f"(lo0), "=f"(hi0) : "l"(acc[k][0]));
        asm("mov.b64 {%0, %1}, %2;" : "=f"(lo1), "=f"(hi1) : "l"(acc[k][1]));
        asm("mov.b64 {%0, %1}, %2;" : "=f"(lo2), "=f"(hi2) : "l"(acc[k][2]));
        asm("mov.b64 {%0, %1}, %2;" : "=f"(lo3), "=f"(hi3) : "l"(acc[k][3]));
        float4 oA = make_float4(lo0 * zA, lo1 * zA, lo2 * zA, lo3 * zA);
        float4 oB = make_float4(hi0 * zB, hi1 * zB, hi2 * zB, hi3 * zB);
        *(float4*)&out[(long long)(r0 + rowA) * FF + cg * 4] = oA;
        *(float4*)&out[(long long)(r0 + rowB) * FF + cg * 4] = oB;
    }
}

// ---------------------------------------------------------------------------
extern "C" void kernel_launch(void* const* d_in, const int* in_sizes, int n_in,
                              void* d_out, int out_size) {
    const float* h   = (const float*)d_in[0];
    const int*   adj = (const int*)d_in[1];
    const float* W   = (const float*)d_in[2];
    const float* a   = (const float*)d_in[3];
    float* out = (float*)d_out;

    k_wh<<<256, 256>>>(h, W);
    k_s12<<<1024, 256>>>(a);
    k_attn<<<256, 256>>>(adj, out);
}

// round 3
// speedup vs baseline: 1.5162x; 1.0632x over previous
#include <cuda_runtime.h>

#define NN 8192
#define FF 256
typedef unsigned long long ull;

// Scratch (static device globals — no allocation allowed)
__device__ float g_Wh[NN * FF];   // 8 MB
__device__ float g_E1[NN];        // exp(s1)
__device__ float g_B1[NN];        // exp(0.2*s1)
__device__ float g_E2[NN];        // exp(s2)
__device__ float g_F2[NN];        // exp(0.2*s2)

// ---------------------------------------------------------------------------
// K1: Wh = h @ W   (8192x256 @ 256x256, fp32)
// ---------------------------------------------------------------------------
__global__ void __launch_bounds__(256) k_wh(const float* __restrict__ h,
                                            const float* __restrict__ W) {
    __shared__ float Ws[32][256];
    __shared__ float hs[32][32];
    int t  = threadIdx.x;
    int r0 = blockIdx.x * 32;

    float acc[32];
#pragma unroll
    for (int r = 0; r < 32; r++) acc[r] = 0.f;

    for (int kc = 0; kc < 8; kc++) {
        __syncthreads();
#pragma unroll
        for (int kk = 0; kk < 32; kk++)
            Ws[kk][t] = W[(kc * 32 + kk) * FF + t];
        {
            int r = t >> 3, c4 = (t & 7) * 4;
            float4 v = *(const float4*)&h[(r0 + r) * FF + kc * 32 + c4];
            hs[r][c4 + 0] = v.x; hs[r][c4 + 1] = v.y;
            hs[r][c4 + 2] = v.z; hs[r][c4 + 3] = v.w;
        }
        __syncthreads();
#pragma unroll
        for (int kk = 0; kk < 32; kk++) {
            float w = Ws[kk][t];
#pragma unroll
            for (int r = 0; r < 32; r++)
                acc[r] = fmaf(hs[r][kk], w, acc[r]);
        }
    }
#pragma unroll
    for (int r = 0; r < 32; r++)
        g_Wh[(r0 + r) * FF + t] = acc[r];
}

// ---------------------------------------------------------------------------
// K1b: s1 = Wh@a1, s2 = Wh@a2; store exp factors.
// exp(lrelu(s1_i+s2_j)) = max(E1_i*E2_j, B1_i*F2_j)   (exp monotone)
// No row-max subtraction needed: |s1+s2| <~ 8 -> exp in [3e-4, 3e3], fp32-safe.
// ---------------------------------------------------------------------------
__global__ void __launch_bounds__(256) k_s12(const float* __restrict__ a) {
    int warp = threadIdx.x >> 5, lane = threadIdx.x & 31;
    int r = blockIdx.x * 8 + warp;
    const float4* wh = (const float4*)&g_Wh[r * FF];
    float v1 = 0.f, v2 = 0.f;
#pragma unroll
    for (int i = 0; i < 2; i++) {
        int k4 = lane + i * 32;
        float4 w  = wh[k4];
        float4 a1 = *(const float4*)&a[k4 * 4];
        float4 a2 = *(const float4*)&a[FF + k4 * 4];
        v1 += w.x * a1.x + w.y * a1.y + w.z * a1.z + w.w * a1.w;
        v2 += w.x * a2.x + w.y * a2.y + w.z * a2.z + w.w * a2.w;
    }
#pragma unroll
    for (int o = 16; o; o >>= 1) {
        v1 += __shfl_down_sync(~0u, v1, o);
        v2 += __shfl_down_sync(~0u, v2, o);
    }
    if (lane == 0) {
        g_E1[r] = __expf(v1);
        g_B1[r] = __expf(0.2f * v1);
        g_E2[r] = __expf(v2);
        g_F2[r] = __expf(0.2f * v2);
    }
}

// ---------------------------------------------------------------------------
// K2: out_i = (sum_j p_ij Wh_j) / Z_i
//     p_ij = adj_ij ? max(E1_i*E2_j, B1_i*F2_j) : 0
// Block = 32 rows, 256 threads, 2 blocks/SM.
// Thread tile: 4 columns (cg) x 4 row-pairs (rg) -> 16 f32x2 accumulators.
// Per j: 4 LDS.64 (p pairs) + 1 LDS.128 (Wh) + 16 FFMA2  => FMA-pipe bound.
// ---------------------------------------------------------------------------
__global__ void __launch_bounds__(256, 2) k_attn(const int* __restrict__ adj,
                                                 float* __restrict__ out) {
    __shared__ float  Whs[32][256];   // 32 KB
    __shared__ float2 ps[32][17];     // [j][row-pair], padded (2-phase min)
    __shared__ float  A1s[32], B1s[32];
    __shared__ float  zinv[32];

    int t  = threadIdx.x;
    int r0 = blockIdx.x * 32;
    int cg = t >> 2;            // column group: cols cg*4 .. cg*4+3
    int rg = t & 3;             // row-pair group: rp = rg*4 .. rg*4+3
    int jj = t & 31;            // p-gen: j index within tile
    int w  = t >> 5;            // warp id: p-gen row-pairs 2w, 2w+1

    if (t < 32) { A1s[t] = g_E1[r0 + t]; B1s[t] = g_B1[r0 + t]; }

    ull acc[4][4];
#pragma unroll
    for (int k = 0; k < 4; k++)
#pragma unroll
        for (int c = 0; c < 4; c++) acc[k][c] = 0ull;
    float zr[4] = {0.f, 0.f, 0.f, 0.f};   // rows 4w..4w+3 (valid in all lanes)

    for (int jt = 0; jt < NN; jt += 32) {
        __syncthreads();   // previous tile's compute done before overwrite

        // ---- Wh tile fill: 2048 float4 / 256 threads = 8 each, coalesced
#pragma unroll
        for (int i = 0; i < 8; i++) {
            int f = i * 256 + t;
            int r = f >> 6, c4 = f & 63;
            *(float4*)&Whs[r][c4 * 4] =
                *(const float4*)&g_Wh[(jt + r) * FF + c4 * 4];
        }

        // ---- p tile + Z partial sums
        {
            float E2j = g_E2[jt + jj];
            float F2j = g_F2[jt + jj];
#pragma unroll
            for (int u = 0; u < 2; u++) {
                int rp = w * 2 + u;
                int ra = rp * 2, rb = rp * 2 + 1;
                int aA = adj[(long long)(r0 + ra) * NN + jt + jj];
                int aB = adj[(long long)(r0 + rb) * NN + jt + jj];
                float pa = aA ? fmaxf(A1s[ra] * E2j, B1s[ra] * F2j) : 0.f;
                float pb = aB ? fmaxf(A1s[rb] * E2j, B1s[rb] * F2j) : 0.f;
                ps[jj][rp] = make_float2(pa, pb);
                float sa = pa, sb = pb;
#pragma unroll
                for (int o = 16; o; o >>= 1) {
                    sa += __shfl_xor_sync(~0u, sa, o);
                    sb += __shfl_xor_sync(~0u, sb, o);
                }
                zr[2 * u]     += sa;
                zr[2 * u + 1] += sb;
            }
        }
        __syncthreads();

        // ---- main accumulate
#pragma unroll 8
        for (int j = 0; j < 32; j++) {
            float4 w4 = *(const float4*)&Whs[j][cg * 4];
            ull wd0, wd1, wd2, wd3;
            asm("mov.b64 %0, {%1, %1};" : "=l"(wd0) : "f"(w4.x));
            asm("mov.b64 %0, {%1, %1};" : "=l"(wd1) : "f"(w4.y));
            asm("mov.b64 %0, {%1, %1};" : "=l"(wd2) : "f"(w4.z));
            asm("mov.b64 %0, {%1, %1};" : "=l"(wd3) : "f"(w4.w));
#pragma unroll
            for (int k = 0; k < 4; k++) {
                ull p2 = *(const ull*)&ps[j][rg * 4 + k];
                asm("fma.rn.f32x2 %0, %1, %2, %0;" : "+l"(acc[k][0]) : "l"(p2), "l"(wd0));
                asm("fma.rn.f32x2 %0, %1, %2, %0;" : "+l"(acc[k][1]) : "l"(p2), "l"(wd1));
                asm("fma.rn.f32x2 %0, %1, %2, %0;" : "+l"(acc[k][2]) : "l"(p2), "l"(wd2));
                asm("fma.rn.f32x2 %0, %1, %2, %0;" : "+l"(acc[k][3]) : "l"(p2), "l"(wd3));
            }
        }
    }

    // ---- Z -> zinv (warp w owns rows 4w..4w+3; zr identical across lanes)
    if ((t & 31) == 0) {
#pragma unroll
        for (int k = 0; k < 4; k++) zinv[w * 4 + k] = __frcp_rn(zr[k]);
    }
    __syncthreads();

    // ---- epilogue: scale + store
#pragma unroll
    for (int k = 0; k < 4; k++) {
        int rowA = rg * 8 + 2 * k;
        int rowB = rowA + 1;
        float zA = zinv[rowA], zB = zinv[rowB];
        float lo0, hi0, lo1, hi1, lo2, hi2, lo3, hi3;
        asm("mov.b64 {%0, %1}, %2;" : "=f"(lo0), "=f"(hi0) : "l"(acc[k][0]));
        asm("mov.b64 {%0, %1}, %2;" : "=f"(lo1), "=f"(hi1) : "l"(acc[k][1]));
        asm("mov.b64 {%0, %1}, %2;" : "=f"(lo2), "=f"(hi2) : "l"(acc[k][2]));
        asm("mov.b64 {%0, %1}, %2;" : "=f"(lo3), "=f"(hi3) : "l"(acc[k][3]));
        float4 oA = make_float4(lo0 * zA, lo1 * zA, lo2 * zA, lo3 * zA);
        float4 oB = make_float4(hi0 * zB, hi1 * zB, hi2 * zB, hi3 * zB);
        *(float4*)&out[(long long)(r0 + rowA) * FF + cg * 4] = oA;
        *(float4*)&out[(long long)(r0 + rowB) * FF + cg * 4] = oB;
    }
}

// ---------------------------------------------------------------------------
extern "C" void kernel_launch(void* const* d_in, const int* in_sizes, int n_in,
                              void* d_out, int out_size) {
    const float* h   = (const float*)d_in[0];
    const int*   adj = (const int*)d_in[1];
    const float* W   = (const float*)d_in[2];
    const float* a   = (const float*)d_in[3];
    float* out = (float*)d_out;

    k_wh<<<256, 256>>>(h, W);
    k_s12<<<1024, 256>>>(a);
    k_attn<<<256, 256>>>(adj, out);
}

// round 7
// speedup vs baseline: 2.0847x; 1.3749x over previous
#include <cuda_runtime.h>
#include <cuda_bf16.h>
#include <cstdint>

#define NN 8192
#define FOUT 256

// ---------------- scratch globals ----------------
__device__ float g_Wh[NN * FOUT];                                  // 8 MB
__device__ __align__(16) __nv_bfloat16 g_WhTi[256 * 256 * 64];     // [jtile][n][hi32|lo32]
__device__ float g_E1[NN], g_B1[NN], g_E2[NN], g_F2[NN];

__device__ __forceinline__ uint32_t s2u(const void* p) {
    uint32_t a;
    asm("{ .reg .u64 t; cvta.to.shared.u64 t, %1; cvt.u32.u64 %0, t; }" : "=r"(a) : "l"(p));
    return a;
}
__device__ __forceinline__ void mma16816(float* d, const uint32_t* a,
                                         uint32_t b0, uint32_t b1) {
    asm volatile(
        "mma.sync.aligned.m16n8k16.row.col.f32.bf16.bf16.f32 "
        "{%0,%1,%2,%3}, {%4,%5,%6,%7}, {%8,%9}, {%0,%1,%2,%3};"
        : "+f"(d[0]), "+f"(d[1]), "+f"(d[2]), "+f"(d[3])
        : "r"(a[0]), "r"(a[1]), "r"(a[2]), "r"(a[3]), "r"(b0), "r"(b1));
}

// ---------------------------------------------------------------------------
// K1: Wh = h @ W   (512 blocks x 256 thr, 16 rows/block)
// ---------------------------------------------------------------------------
__global__ void __launch_bounds__(256) k_wh(const float* __restrict__ h,
                                            const float* __restrict__ W) {
    __shared__ float Ws[32][256];
    __shared__ float hs[16][32];
    int t = threadIdx.x, r0 = blockIdx.x * 16;
    float acc[16];
#pragma unroll
    for (int r = 0; r < 16; r++) acc[r] = 0.f;
    for (int kc = 0; kc < 8; kc++) {
        __syncthreads();
#pragma unroll
        for (int kk = 0; kk < 32; kk++) Ws[kk][t] = W[(kc * 32 + kk) * FOUT + t];
        {
            int r = t >> 4, c2 = (t & 15) * 2;
            float2 v = *(const float2*)&h[(r0 + r) * FOUT + kc * 32 + c2];
            hs[r][c2] = v.x; hs[r][c2 + 1] = v.y;
        }
        __syncthreads();
#pragma unroll
        for (int kk = 0; kk < 32; kk++) {
            float w = Ws[kk][t];
#pragma unroll
            for (int r = 0; r < 16; r++) acc[r] = fmaf(hs[r][kk], w, acc[r]);
        }
    }
#pragma unroll
    for (int r = 0; r < 16; r++) g_Wh[(r0 + r) * FOUT + t] = acc[r];
}

// ---------------------------------------------------------------------------
// K1t: WhTi[jtile kb][col n][64] = [hi bf16 of Wh[kb*32+r][n], r=0..31 | lo ...]
// Even r in LOW 16 bits of each packed pair (matches B-fragment layout).
// ---------------------------------------------------------------------------
__global__ void __launch_bounds__(256) k_tr() {
    int t = threadIdx.x, kb = blockIdx.x;
    float v[32];
#pragma unroll
    for (int r = 0; r < 32; r++) v[r] = g_Wh[(kb * 32 + r) * FOUT + t];  // coalesced
    uint32_t hi16[16], lo16[16];
#pragma unroll
    for (int rp = 0; rp < 16; rp++) {
        float v0 = v[2 * rp], v1 = v[2 * rp + 1];
        __nv_bfloat16 h0 = __float2bfloat16(v0), h1 = __float2bfloat16(v1);
        float l0 = v0 - __bfloat162float(h0), l1 = v1 - __bfloat162float(h1);
        __nv_bfloat16 g0 = __float2bfloat16(l0), g1 = __float2bfloat16(l1);
        hi16[rp] = (uint32_t)__bfloat16_as_ushort(h1) << 16 | __bfloat16_as_ushort(h0);
        lo16[rp] = (uint32_t)__bfloat16_as_ushort(g1) << 16 | __bfloat16_as_ushort(g0);
    }
    __nv_bfloat16* dst = &g_WhTi[((size_t)kb * 256 + t) * 64];
#pragma unroll
    for (int s = 0; s < 4; s++) {
        *(uint4*)(dst + s * 8)      = make_uint4(hi16[4*s], hi16[4*s+1], hi16[4*s+2], hi16[4*s+3]);
        *(uint4*)(dst + 32 + s * 8) = make_uint4(lo16[4*s], lo16[4*s+1], lo16[4*s+2], lo16[4*s+3]);
    }
}

// ---------------------------------------------------------------------------
// K1b: s1,s2 -> exp factors. exp(lrelu(s1+s2)) = max(E1*E2, B1*F2).
// ---------------------------------------------------------------------------
__global__ void __launch_bounds__(256) k_s12(const float* __restrict__ a) {
    int warp = threadIdx.x >> 5, lane = threadIdx.x & 31;
    int r = blockIdx.x * 8 + warp;
    const float4* wh = (const float4*)&g_Wh[r * FOUT];
    float v1 = 0.f, v2 = 0.f;
#pragma unroll
    for (int i = 0; i < 2; i++) {
        int k4 = lane + i * 32;
        float4 w  = wh[k4];
        float4 a1 = *(const float4*)&a[k4 * 4];
        float4 a2 = *(const float4*)&a[FOUT + k4 * 4];
        v1 += w.x * a1.x + w.y * a1.y + w.z * a1.z + w.w * a1.w;
        v2 += w.x * a2.x + w.y * a2.y + w.z * a2.z + w.w * a2.w;
    }
#pragma unroll
    for (int o = 16; o; o >>= 1) {
        v1 += __shfl_down_sync(~0u, v1, o);
        v2 += __shfl_down_sync(~0u, v2, o);
    }
    if (lane == 0) {
        g_E1[r] = __expf(v1);  g_B1[r] = __expf(0.2f * v1);
        g_E2[r] = __expf(v2);  g_F2[r] = __expf(0.2f * v2);
    }
}

// ---------------------------------------------------------------------------
// K2: fused P-gen + HMMA bf16-split GEMM + softmax normalize.
// 128 CTAs = 64 row-blocks (M=128) x 2 col-blocks (N=128). Full j loop per CTA.
// ---------------------------------------------------------------------------
__global__ void __launch_bounds__(256) k_attn(const int* __restrict__ adj,
                                              float* __restrict__ out) {
    __shared__ uint32_t PH[2560];    // P hi: 128 rows x 20 words (80B stride)
    __shared__ uint32_t PL[2560];    // P lo
    __shared__ uint32_t WhS[4608];   // Wh tile: 128 n x 36 words (144B stride)
    __shared__ float Zs[128];

    int t = threadIdx.x;
    int rb = blockIdx.x >> 1, cb = blockIdx.x & 1;
    int r0 = rb * 128;
    int w = t >> 5, lane = t & 31;
    int kp = t & 15, rsub = t >> 4;
    int g = lane >> 2, quad = lane & 3;
    int mb = (w >> 1) * 32;          // warp m base (0,32,64,96)
    int nb = (w & 1) * 64;           // warp n base (0,64) local

    float e1r[8], b1r[8], zacc[8];
#pragma unroll
    for (int it = 0; it < 8; it++) {
        int r = it * 16 + rsub;
        e1r[it] = g_E1[r0 + r];
        b1r[it] = g_B1[r0 + r];
        zacc[it] = 0.f;
    }

    float acc[2][8][4];
#pragma unroll
    for (int mt = 0; mt < 2; mt++)
#pragma unroll
        for (int nt = 0; nt < 8; nt++)
#pragma unroll
            for (int e = 0; e < 4; e++) acc[mt][nt][e] = 0.f;

    // prefetch adj tile 0
    int2 adjv[8];
#pragma unroll
    for (int it = 0; it < 8; it++)
        adjv[it] = *(const int2*)&adj[(long long)(r0 + it * 16 + rsub) * NN + 2 * kp];

    uint32_t whb = s2u(WhS);

    for (int i = 0; i < 256; i++) {
        // ---- Wh tile via cp.async (L2-resident WhTi, pre-split hi/lo)
        {
            int n = t >> 1, half = t & 1;
            const __nv_bfloat16* src =
                &g_WhTi[((size_t)i * 256 + cb * 128 + n) * 64 + half * 32];
            uint32_t d = whb + (uint32_t)(n * 144 + half * 64);
#pragma unroll
            for (int s4 = 0; s4 < 4; s4++)
                asm volatile("cp.async.cg.shared.global [%0], [%1], 16;"
                             :: "r"(d + s4 * 16), "l"((const char*)src + s4 * 16) : "memory");
            asm volatile("cp.async.commit_group;" ::: "memory");
        }

        // ---- P-gen (rows it*16+rsub, j pair 2kp) from prefetched adj
        {
            float2 e2 = *(const float2*)&g_E2[i * 32 + 2 * kp];
            float2 f2 = *(const float2*)&g_F2[i * 32 + 2 * kp];
#pragma unroll
            for (int it = 0; it < 8; it++) {
                int r = it * 16 + rsub;
                float p0 = adjv[it].x ? fmaxf(e1r[it] * e2.x, b1r[it] * f2.x) : 0.f;
                float p1 = adjv[it].y ? fmaxf(e1r[it] * e2.y, b1r[it] * f2.y) : 0.f;
                zacc[it] += p0 + p1;
                uint32_t hp;
                asm("cvt.rn.bf16x2.f32 %0, %1, %2;" : "=r"(hp) : "f"(p1), "f"(p0));
                float h0f = __uint_as_float(hp << 16);
                float h1f = __uint_as_float(hp & 0xffff0000u);
                uint32_t lp;
                asm("cvt.rn.bf16x2.f32 %0, %1, %2;" : "=r"(lp)
                    : "f"(p1 - h1f), "f"(p0 - h0f));
                PH[r * 20 + kp] = hp;
                PL[r * 20 + kp] = lp;
            }
        }

        // ---- prefetch adj tile i+1 (hidden under MMA)
        if (i < 255) {
#pragma unroll
            for (int it = 0; it < 8; it++)
                adjv[it] = *(const int2*)&adj[(long long)(r0 + it * 16 + rsub) * NN
                                             + (i + 1) * 32 + 2 * kp];
        }

        asm volatile("cp.async.wait_group 0;" ::: "memory");
        __syncthreads();

        // ---- MMA: 2 k-steps x (2m x 8n) x 3 split terms
#pragma unroll
        for (int ks = 0; ks < 2; ks++) {
            uint32_t Ah[2][4], Al[2][4], Bh[8][2], Bl[8][2];
#pragma unroll
            for (int mt = 0; mt < 2; mt++) {
                int wi = (mb + mt * 16 + g) * 20 + ks * 8 + quad;
                Ah[mt][0] = PH[wi];     Ah[mt][1] = PH[wi + 160];
                Ah[mt][2] = PH[wi + 4]; Ah[mt][3] = PH[wi + 164];
                Al[mt][0] = PL[wi];     Al[mt][1] = PL[wi + 160];
                Al[mt][2] = PL[wi + 4]; Al[mt][3] = PL[wi + 164];
            }
#pragma unroll
            for (int nt = 0; nt < 8; nt++) {
                int wi = (nb + nt * 8 + g) * 36 + ks * 8 + quad;
                Bh[nt][0] = WhS[wi];      Bh[nt][1] = WhS[wi + 4];
                Bl[nt][0] = WhS[wi + 16]; Bl[nt][1] = WhS[wi + 20];
            }
#pragma unroll
            for (int nt = 0; nt < 8; nt++) {
                mma16816(acc[0][nt], Ah[0], Bh[nt][0], Bh[nt][1]);
                mma16816(acc[1][nt], Ah[1], Bh[nt][0], Bh[nt][1]);
            }
#pragma unroll
            for (int nt = 0; nt < 8; nt++) {
                mma16816(acc[0][nt], Al[0], Bh[nt][0], Bh[nt][1]);
                mma16816(acc[1][nt], Al[1], Bh[nt][0], Bh[nt][1]);
            }
#pragma unroll
            for (int nt = 0; nt < 8; nt++) {
                mma16816(acc[0][nt], Ah[0], Bl[nt][0], Bl[nt][1]);
                mma16816(acc[1][nt], Ah[1], Bl[nt][0], Bl[nt][1]);
            }
        }
        __syncthreads();   // MMA reads done before next tile's stores
    }

    // ---- Z: reduce over 16 kp lanes per row
#pragma unroll
    for (int it = 0; it < 8; it++) {
        float z = zacc[it];
        z += __shfl_xor_sync(~0u, z, 1);
        z += __shfl_xor_sync(~0u, z, 2);
        z += __shfl_xor_sync(~0u, z, 4);
        z += __shfl_xor_sync(~0u, z, 8);
        if ((lane & 15) == 0) Zs[it * 16 + rsub] = z;
    }
    __syncthreads();

    // ---- epilogue: divide by Z, store
#pragma unroll
    for (int mt = 0; mt < 2; mt++) {
        int rl = mb + mt * 16 + g;
        float zi0 = __frcp_rn(Zs[rl]);
        float zi1 = __frcp_rn(Zs[rl + 8]);
#pragma unroll
        for (int nt = 0; nt < 8; nt++) {
            int c = cb * 128 + nb + nt * 8 + quad * 2;
            *(float2*)&out[(size_t)(r0 + rl) * FOUT + c] =
                make_float2(acc[mt][nt][0] * zi0, acc[mt][nt][1] * zi0);
            *(float2*)&out[(size_t)(r0 + rl + 8) * FOUT + c] =
                make_float2(acc[mt][nt][2] * zi1, acc[mt][nt][3] * zi1);
        }
    }
}

// ---------------------------------------------------------------------------
extern "C" void kernel_launch(void* const* d_in, const int* in_sizes, int n_in,
                              void* d_out, int out_size) {
    const float* h   = (const float*)d_in[0];
    const int*   adj = (const int*)d_in[1];
    const float* W   = (const float*)d_in[2];
    const float* a   = (const float*)d_in[3];
    float* out = (float*)d_out;

    k_wh<<<512, 256>>>(h, W);
    k_tr<<<256, 256>>>();
    k_s12<<<1024, 256>>>(a);
    k_attn<<<128, 256>>>(adj, out);
}

// round 9
// speedup vs baseline: 2.6557x; 1.2739x over previous
#include <cuda_runtime.h>
#include <cuda_bf16.h>
#include <cstdint>

#define NN 8192
#define FOUT 256

// smem layout (bytes, dynamic)
#define PH_OFF 0u
#define PH_SZ  10240u            // 128 rows x 80B
#define PL_OFF 20480u
#define WH_OFF 40960u
#define WH_SZ  18432u            // 128 n x 144B
#define ZS_OFF 77824u
#define SM_TOT 78336u

// ---------------- scratch globals ----------------
__device__ float g_Wh[NN * FOUT];                                  // 8 MB
__device__ __align__(16) __nv_bfloat16 g_WhTi[256 * 256 * 64];     // [jtile][n][hi32|lo32]
__device__ float g_E1[NN], g_B1[NN], g_E2[NN], g_F2[NN];

__device__ __forceinline__ uint32_t s2u(const void* p) {
    uint32_t a;
    asm("{ .reg .u64 t; cvta.to.shared.u64 t, %1; cvt.u32.u64 %0, t; }" : "=r"(a) : "l"(p));
    return a;
}
__device__ __forceinline__ void mma16816(float* d, const uint32_t* a,
                                         uint32_t b0, uint32_t b1) {
    asm volatile(
        "mma.sync.aligned.m16n8k16.row.col.f32.bf16.bf16.f32 "
        "{%0,%1,%2,%3}, {%4,%5,%6,%7}, {%8,%9}, {%0,%1,%2,%3};"
        : "+f"(d[0]), "+f"(d[1]), "+f"(d[2]), "+f"(d[3])
        : "r"(a[0]), "r"(a[1]), "r"(a[2]), "r"(a[3]), "r"(b0), "r"(b1));
}
__device__ __forceinline__ void ldsm4(uint32_t* r, uint32_t addr) {
    asm volatile("ldmatrix.sync.aligned.m8n8.x4.shared.b16 {%0,%1,%2,%3}, [%4];"
                 : "=r"(r[0]), "=r"(r[1]), "=r"(r[2]), "=r"(r[3]) : "r"(addr));
}

// ---------------------------------------------------------------------------
// K1: Wh = h @ W   (512 blocks x 256 thr, 16 rows/block)
// ---------------------------------------------------------------------------
__global__ void __launch_bounds__(256) k_wh(const float* __restrict__ h,
                                            const float* __restrict__ W) {
    __shared__ float Ws[32][256];
    __shared__ float hs[16][32];
    int t = threadIdx.x, r0 = blockIdx.x * 16;
    float acc[16];
#pragma unroll
    for (int r = 0; r < 16; r++) acc[r] = 0.f;
    for (int kc = 0; kc < 8; kc++) {
        __syncthreads();
#pragma unroll
        for (int kk = 0; kk < 32; kk++) Ws[kk][t] = W[(kc * 32 + kk) * FOUT + t];
        {
            int r = t >> 4, c2 = (t & 15) * 2;
            float2 v = *(const float2*)&h[(r0 + r) * FOUT + kc * 32 + c2];
            hs[r][c2] = v.x; hs[r][c2 + 1] = v.y;
        }
        __syncthreads();
#pragma unroll
        for (int kk = 0; kk < 32; kk++) {
            float w = Ws[kk][t];
#pragma unroll
            for (int r = 0; r < 16; r++) acc[r] = fmaf(hs[r][kk], w, acc[r]);
        }
    }
#pragma unroll
    for (int r = 0; r < 16; r++) g_Wh[(r0 + r) * FOUT + t] = acc[r];
}

// ---------------------------------------------------------------------------
// K1t: WhTi[kb][n][64] = [hi bf16 of Wh[kb*32+r][n] r=0..31 | lo ...]
// ---------------------------------------------------------------------------
__global__ void __launch_bounds__(256) k_tr() {
    int t = threadIdx.x, kb = blockIdx.x;
    float v[32];
#pragma unroll
    for (int r = 0; r < 32; r++) v[r] = g_Wh[(kb * 32 + r) * FOUT + t];
    uint32_t hi16[16], lo16[16];
#pragma unroll
    for (int rp = 0; rp < 16; rp++) {
        float v0 = v[2 * rp], v1 = v[2 * rp + 1];
        __nv_bfloat16 h0 = __float2bfloat16(v0), h1 = __float2bfloat16(v1);
        float l0 = v0 - __bfloat162float(h0), l1 = v1 - __bfloat162float(h1);
        __nv_bfloat16 g0 = __float2bfloat16(l0), g1 = __float2bfloat16(l1);
        hi16[rp] = (uint32_t)__bfloat16_as_ushort(h1) << 16 | __bfloat16_as_ushort(h0);
        lo16[rp] = (uint32_t)__bfloat16_as_ushort(g1) << 16 | __bfloat16_as_ushort(g0);
    }
    __nv_bfloat16* dst = &g_WhTi[((size_t)kb * 256 + t) * 64];
#pragma unroll
    for (int s = 0; s < 4; s++) {
        *(uint4*)(dst + s * 8)      = make_uint4(hi16[4*s], hi16[4*s+1], hi16[4*s+2], hi16[4*s+3]);
        *(uint4*)(dst + 32 + s * 8) = make_uint4(lo16[4*s], lo16[4*s+1], lo16[4*s+2], lo16[4*s+3]);
    }
}

// ---------------------------------------------------------------------------
// K1b: s1,s2 -> exp factors. exp(lrelu(s1+s2)) = max(E1*E2, B1*F2).
// ---------------------------------------------------------------------------
__global__ void __launch_bounds__(256) k_s12(const float* __restrict__ a) {
    int warp = threadIdx.x >> 5, lane = threadIdx.x & 31;
    int r = blockIdx.x * 8 + warp;
    const float4* wh = (const float4*)&g_Wh[r * FOUT];
    float v1 = 0.f, v2 = 0.f;
#pragma unroll
    for (int i = 0; i < 2; i++) {
        int k4 = lane + i * 32;
        float4 w  = wh[k4];
        float4 a1 = *(const float4*)&a[k4 * 4];
        float4 a2 = *(const float4*)&a[FOUT + k4 * 4];
        v1 += w.x * a1.x + w.y * a1.y + w.z * a1.z + w.w * a1.w;
        v2 += w.x * a2.x + w.y * a2.y + w.z * a2.z + w.w * a2.w;
    }
#pragma unroll
    for (int o = 16; o; o >>= 1) {
        v1 += __shfl_down_sync(~0u, v1, o);
        v2 += __shfl_down_sync(~0u, v2, o);
    }
    if (lane == 0) {
        g_E1[r] = __expf(v1);  g_B1[r] = __expf(0.2f * v1);
        g_E2[r] = __expf(v2);  g_F2[r] = __expf(0.2f * v2);
    }
}

// ---------------------------------------------------------------------------
// K2: fused P-gen + HMMA, software-pipelined (double-buffered P & Wh tiles).
// 128 CTAs = 64 row-blocks (M=128) x 2 col-blocks (N=128).
// Per iter: wait cp(i); sync; issue cp(i+1); gen P(i+1)->buf^1; MMA(i)<-buf.
// ---------------------------------------------------------------------------
__global__ void __launch_bounds__(256, 1) k_attn(const int* __restrict__ adj,
                                                 float* __restrict__ out) {
    extern __shared__ char sm[];
    uint32_t sb = s2u(sm);

    int t = threadIdx.x;
    int rb = blockIdx.x >> 1, cb = blockIdx.x & 1;
    int r0 = rb * 128;
    int w = t >> 5, lane = t & 31;
    int kp = t & 15, rsub = t >> 4;
    int g = lane >> 2, quad = lane & 3;
    int mb = (w >> 1) * 32;
    int nb = (w & 1) * 64;

    // ldmatrix base addresses (buf 0)
    uint32_t aAddr = sb + PH_OFF + (uint32_t)((mb + (lane & 15)) * 80 + (lane >> 4) * 16);
    uint32_t bAddr = sb + WH_OFF +
        (uint32_t)((nb + (lane >> 4) * 8 + (lane & 7)) * 144 + ((lane >> 3) & 1) * 16);

    // cp.async dst base
    int cn = t >> 1, chalf = t & 1;
    uint32_t cpDst = sb + WH_OFF + (uint32_t)(cn * 144 + chalf * 64);
    const char* cpSrcBase =
        (const char*)&g_WhTi[((size_t)cb * 128 + cn) * 64 + chalf * 32];

    float e1r[8], b1r[8], zacc[8];
#pragma unroll
    for (int it = 0; it < 8; it++) {
        int r = it * 16 + rsub;
        e1r[it] = g_E1[r0 + r];
        b1r[it] = g_B1[r0 + r];
        zacc[it] = 0.f;
    }

    float acc[2][8][4];
#pragma unroll
    for (int mt = 0; mt < 2; mt++)
#pragma unroll
        for (int nt = 0; nt < 8; nt++)
#pragma unroll
            for (int e = 0; e < 4; e++) acc[mt][nt][e] = 0.f;

    int2 adjv[8];
#pragma unroll
    for (int it = 0; it < 8; it++)
        adjv[it] = *(const int2*)&adj[(long long)(r0 + it * 16 + rsub) * NN + 2 * kp];

    // P-gen into buffer buf for tile ti (consumes adjv)
    auto gen = [&](int ti, uint32_t buf) {
        char* phb = sm + PH_OFF + buf * PH_SZ;
        char* plb = sm + PL_OFF + buf * PH_SZ;
        float2 e2 = *(const float2*)&g_E2[ti * 32 + 2 * kp];
        float2 f2 = *(const float2*)&g_F2[ti * 32 + 2 * kp];
#pragma unroll
        for (int it = 0; it < 8; it++) {
            int r = it * 16 + rsub;
            float p0 = adjv[it].x ? fmaxf(e1r[it] * e2.x, b1r[it] * f2.x) : 0.f;
            float p1 = adjv[it].y ? fmaxf(e1r[it] * e2.y, b1r[it] * f2.y) : 0.f;
            zacc[it] += p0 + p1;
            uint32_t hp;
            asm("cvt.rn.bf16x2.f32 %0, %1, %2;" : "=r"(hp) : "f"(p1), "f"(p0));
            float h0f = __uint_as_float(hp << 16);
            float h1f = __uint_as_float(hp & 0xffff0000u);
            uint32_t lp;
            asm("cvt.rn.bf16x2.f32 %0, %1, %2;" : "=r"(lp) : "f"(p1 - h1f), "f"(p0 - h0f));
            *(uint32_t*)(phb + r * 80 + kp * 4) = hp;
            *(uint32_t*)(plb + r * 80 + kp * 4) = lp;
        }
    };
    auto cpWh = [&](int ti, uint32_t buf) {
        const char* src = cpSrcBase + (size_t)ti * 32768;   // 256 n * 64 bf16 * 2B per tile
        uint32_t d = cpDst + buf * WH_SZ;
#pragma unroll
        for (int s4 = 0; s4 < 4; s4++)
            asm volatile("cp.async.cg.shared.global [%0], [%1], 16;"
                         :: "r"(d + s4 * 16), "l"(src + s4 * 16) : "memory");
        asm volatile("cp.async.commit_group;" ::: "memory");
    };

    // ---- prologue: tile 0
    cpWh(0, 0);
    gen(0, 0);
#pragma unroll
    for (int it = 0; it < 8; it++)
        adjv[it] = *(const int2*)&adj[(long long)(r0 + it * 16 + rsub) * NN + 32 + 2 * kp];

    for (int i = 0; i < 256; i++) {
        uint32_t cur = i & 1, nxt = cur ^ 1;
        asm volatile("cp.async.wait_group 0;" ::: "memory");
        __syncthreads();

        if (i < 255) {
            cpWh(i + 1, nxt);
            gen(i + 1, nxt);
            if (i < 254) {
#pragma unroll
                for (int it = 0; it < 8; it++)
                    adjv[it] = *(const int2*)&adj[(long long)(r0 + it * 16 + rsub) * NN
                                                 + (i + 2) * 32 + 2 * kp];
            }
        }

        // ---- MMA(i) from buffer cur
        uint32_t aH = aAddr + cur * PH_SZ;
        uint32_t aL = aH + 20480u;            // PL_OFF - PH_OFF
        uint32_t bB = bAddr + cur * WH_SZ;
#pragma unroll
        for (int ks = 0; ks < 2; ks++) {
            uint32_t Ah[2][4], Al[2][4], Bh[4][4], Bl[4][4];
            ldsm4(Ah[0], aH + ks * 32);
            ldsm4(Ah[1], aH + ks * 32 + 1280);
            ldsm4(Al[0], aL + ks * 32);
            ldsm4(Al[1], aL + ks * 32 + 1280);
#pragma unroll
            for (int np = 0; np < 4; np++) {
                ldsm4(Bh[np], bB + np * 2304 + ks * 32);
                ldsm4(Bl[np], bB + np * 2304 + ks * 32 + 64);
            }
#pragma unroll
            for (int np = 0; np < 4; np++) {
                mma16816(acc[0][2*np],   Ah[0], Bh[np][0], Bh[np][1]);
                mma16816(acc[1][2*np],   Ah[1], Bh[np][0], Bh[np][1]);
                mma16816(acc[0][2*np+1], Ah[0], Bh[np][2], Bh[np][3]);
                mma16816(acc[1][2*np+1], Ah[1], Bh[np][2], Bh[np][3]);
            }
#pragma unroll
            for (int np = 0; np < 4; np++) {
                mma16816(acc[0][2*np],   Al[0], Bh[np][0], Bh[np][1]);
                mma16816(acc[1][2*np],   Al[1], Bh[np][0], Bh[np][1]);
                mma16816(acc[0][2*np+1], Al[0], Bh[np][2], Bh[np][3]);
                mma16816(acc[1][2*np+1], Al[1], Bh[np][2], Bh[np][3]);
            }
#pragma unroll
            for (int np = 0; np < 4; np++) {
                mma16816(acc[0][2*np],   Ah[0], Bl[np][0], Bl[np][1]);
                mma16816(acc[1][2*np],   Ah[1], Bl[np][0], Bl[np][1]);
                mma16816(acc[0][2*np+1], Ah[0], Bl[np][2], Bl[np][3]);
                mma16816(acc[1][2*np+1], Ah[1], Bl[np][2], Bl[np][3]);
            }
        }
    }

    // ---- Z reduce (16 kp lanes per row)
    float* Zs = (float*)(sm + ZS_OFF);
#pragma unroll
    for (int it = 0; it < 8; it++) {
        float z = zacc[it];
        z += __shfl_xor_sync(~0u, z, 1);
        z += __shfl_xor_sync(~0u, z, 2);
        z += __shfl_xor_sync(~0u, z, 4);
        z += __shfl_xor_sync(~0u, z, 8);
        if ((lane & 15) == 0) Zs[it * 16 + rsub] = z;
    }
    __syncthreads();

    // ---- epilogue
#pragma unroll
    for (int mt = 0; mt < 2; mt++) {
        int rl = mb + mt * 16 + g;
        float zi0 = __frcp_rn(Zs[rl]);
        float zi1 = __frcp_rn(Zs[rl + 8]);
#pragma unroll
        for (int nt = 0; nt < 8; nt++) {
            int c = cb * 128 + nb + nt * 8 + quad * 2;
            *(float2*)&out[(size_t)(r0 + rl) * FOUT + c] =
                make_float2(acc[mt][nt][0] * zi0, acc[mt][nt][1] * zi0);
            *(float2*)&out[(size_t)(r0 + rl + 8) * FOUT + c] =
                make_float2(acc[mt][nt][2] * zi1, acc[mt][nt][3] * zi1);
        }
    }
}

// ---------------------------------------------------------------------------
extern "C" void kernel_launch(void* const* d_in, const int* in_sizes, int n_in,
                              void* d_out, int out_size) {
    const float* h   = (const float*)d_in[0];
    const int*   adj = (const int*)d_in[1];
    const float* W   = (const float*)d_in[2];
    const float* a   = (const float*)d_in[3];
    float* out = (float*)d_out;

    cudaFuncSetAttribute(k_attn, cudaFuncAttributeMaxDynamicSharedMemorySize, SM_TOT);

    k_wh<<<512, 256>>>(h, W);
    k_tr<<<256, 256>>>();
    k_s12<<<1024, 256>>>(a);
    k_attn<<<128, 256, SM_TOT>>>(adj, out);
}

// round 11
// speedup vs baseline: 3.1300x; 1.1786x over previous
#include <cuda_runtime.h>
#include <cuda_bf16.h>
#include <cstdint>

#define NN 8192
#define FOUT 256

// smem layout (bytes, dynamic) — M=64 tiles
#define PH_OFF 0u
#define PH_SZ  5120u             // 64 rows x 80B
#define PL_OFF 10240u
#define WH_OFF 20480u
#define WH_SZ  18432u            // 128 n x 144B
#define ZS_OFF 57344u
#define SM_TOT 57600u

// ---------------- scratch globals ----------------
__device__ float g_Wh[NN * FOUT];                                  // 8 MB
__device__ __align__(16) __nv_bfloat16 g_WhTi[256 * 256 * 64];     // [jtile][n][hi32|lo32]
__device__ float g_E1[NN], g_B1[NN], g_E2[NN], g_F2[NN];

__device__ __forceinline__ uint32_t s2u(const void* p) {
    uint32_t a;
    asm("{ .reg .u64 t; cvta.to.shared.u64 t, %1; cvt.u32.u64 %0, t; }" : "=r"(a) : "l"(p));
    return a;
}
__device__ __forceinline__ void mma16816(float* d, const uint32_t* a,
                                         uint32_t b0, uint32_t b1) {
    asm volatile(
        "mma.sync.aligned.m16n8k16.row.col.f32.bf16.bf16.f32 "
        "{%0,%1,%2,%3}, {%4,%5,%6,%7}, {%8,%9}, {%0,%1,%2,%3};"
        : "+f"(d[0]), "+f"(d[1]), "+f"(d[2]), "+f"(d[3])
        : "r"(a[0]), "r"(a[1]), "r"(a[2]), "r"(a[3]), "r"(b0), "r"(b1));
}
__device__ __forceinline__ void ldsm4(uint32_t* r, uint32_t addr) {
    asm volatile("ldmatrix.sync.aligned.m8n8.x4.shared.b16 {%0,%1,%2,%3}, [%4];"
                 : "=r"(r[0]), "=r"(r[1]), "=r"(r[2]), "=r"(r[3]) : "r"(addr));
}

// ---------------------------------------------------------------------------
// K1: Wh = h @ W   (512 blocks x 256 thr, 16 rows/block)
// ---------------------------------------------------------------------------
__global__ void __launch_bounds__(256) k_wh(const float* __restrict__ h,
                                            const float* __restrict__ W) {
    __shared__ float Ws[32][256];
    __shared__ float hs[16][32];
    int t = threadIdx.x, r0 = blockIdx.x * 16;
    float acc[16];
#pragma unroll
    for (int r = 0; r < 16; r++) acc[r] = 0.f;
    for (int kc = 0; kc < 8; kc++) {
        __syncthreads();
#pragma unroll
        for (int kk = 0; kk < 32; kk++) Ws[kk][t] = W[(kc * 32 + kk) * FOUT + t];
        {
            int r = t >> 4, c2 = (t & 15) * 2;
            float2 v = *(const float2*)&h[(r0 + r) * FOUT + kc * 32 + c2];
            hs[r][c2] = v.x; hs[r][c2 + 1] = v.y;
        }
        __syncthreads();
#pragma unroll
        for (int kk = 0; kk < 32; kk++) {
            float w = Ws[kk][t];
#pragma unroll
            for (int r = 0; r < 16; r++) acc[r] = fmaf(hs[r][kk], w, acc[r]);
        }
    }
#pragma unroll
    for (int r = 0; r < 16; r++) g_Wh[(r0 + r) * FOUT + t] = acc[r];
}

// ---------------------------------------------------------------------------
// K1t: WhTi[kb][n][64] = [hi bf16 of Wh[kb*32+r][n] r=0..31 | lo ...]
// ---------------------------------------------------------------------------
__global__ void __launch_bounds__(256) k_tr() {
    int t = threadIdx.x, kb = blockIdx.x;
    float v[32];
#pragma unroll
    for (int r = 0; r < 32; r++) v[r] = g_Wh[(kb * 32 + r) * FOUT + t];
    uint32_t hi16[16], lo16[16];
#pragma unroll
    for (int rp = 0; rp < 16; rp++) {
        float v0 = v[2 * rp], v1 = v[2 * rp + 1];
        __nv_bfloat16 h0 = __float2bfloat16(v0), h1 = __float2bfloat16(v1);
        float l0 = v0 - __bfloat162float(h0), l1 = v1 - __bfloat162float(h1);
        __nv_bfloat16 g0 = __float2bfloat16(l0), g1 = __float2bfloat16(l1);
        hi16[rp] = (uint32_t)__bfloat16_as_ushort(h1) << 16 | __bfloat16_as_ushort(h0);
        lo16[rp] = (uint32_t)__bfloat16_as_ushort(g1) << 16 | __bfloat16_as_ushort(g0);
    }
    __nv_bfloat16* dst = &g_WhTi[((size_t)kb * 256 + t) * 64];
#pragma unroll
    for (int s = 0; s < 4; s++) {
        *(uint4*)(dst + s * 8)      = make_uint4(hi16[4*s], hi16[4*s+1], hi16[4*s+2], hi16[4*s+3]);
        *(uint4*)(dst + 32 + s * 8) = make_uint4(lo16[4*s], lo16[4*s+1], lo16[4*s+2], lo16[4*s+3]);
    }
}

// ---------------------------------------------------------------------------
// K1b: s1,s2 -> exp factors. exp(lrelu(s1+s2)) = max(E1*E2, B1*F2).
// ---------------------------------------------------------------------------
__global__ void __launch_bounds__(256) k_s12(const float* __restrict__ a) {
    int warp = threadIdx.x >> 5, lane = threadIdx.x & 31;
    int r = blockIdx.x * 8 + warp;
    const float4* wh = (const float4*)&g_Wh[r * FOUT];
    float v1 = 0.f, v2 = 0.f;
#pragma unroll
    for (int i = 0; i < 2; i++) {
        int k4 = lane + i * 32;
        float4 w  = wh[k4];
        float4 a1 = *(const float4*)&a[k4 * 4];
        float4 a2 = *(const float4*)&a[FOUT + k4 * 4];
        v1 += w.x * a1.x + w.y * a1.y + w.z * a1.z + w.w * a1.w;
        v2 += w.x * a2.x + w.y * a2.y + w.z * a2.z + w.w * a2.w;
    }
#pragma unroll
    for (int o = 16; o; o >>= 1) {
        v1 += __shfl_down_sync(~0u, v1, o);
        v2 += __shfl_down_sync(~0u, v2, o);
    }
    if (lane == 0) {
        g_E1[r] = __expf(v1);  g_B1[r] = __expf(0.2f * v1);
        g_E2[r] = __expf(v2);  g_F2[r] = __expf(0.2f * v2);
    }
}

// ---------------------------------------------------------------------------
// K2: fused P-gen + HMMA, pipelined, M=64 tiles for 2 CTAs/SM.
// 256 CTAs = 128 row-blocks (M=64) x 2 col-blocks (N=128).
// 8 warps = 4m x 2n; warp tile 16m x 64n -> acc 8nt x 4 = 32 regs.
// ---------------------------------------------------------------------------
__global__ void __launch_bounds__(256, 2) k_attn(const int* __restrict__ adj,
                                                 float* __restrict__ out) {
    extern __shared__ char sm[];
    uint32_t sb = s2u(sm);

    int t = threadIdx.x;
    int rb = blockIdx.x >> 1, cb = blockIdx.x & 1;
    int r0 = rb * 64;
    int w = t >> 5, lane = t & 31;
    int kp = t & 15, rsub = t >> 4;
    int g = lane >> 2, quad = lane & 3;
    int mb = (w >> 1) * 16;          // warp m base: 0,16,32,48
    int nb = (w & 1) * 64;           // warp n base local

    // ldmatrix base addresses (buf 0)
    uint32_t aAddr = sb + PH_OFF + (uint32_t)((mb + (lane & 15)) * 80 + (lane >> 4) * 16);
    uint32_t bAddr = sb + WH_OFF +
        (uint32_t)((nb + (lane >> 4) * 8 + (lane & 7)) * 144 + ((lane >> 3) & 1) * 16);

    // cp.async dst base
    int cn = t >> 1, chalf = t & 1;
    uint32_t cpDst = sb + WH_OFF + (uint32_t)(cn * 144 + chalf * 64);
    const char* cpSrcBase =
        (const char*)&g_WhTi[((size_t)cb * 128 + cn) * 64 + chalf * 32];

    float e1r[4], b1r[4], zacc[4];
#pragma unroll
    for (int it = 0; it < 4; it++) {
        int r = it * 16 + rsub;
        e1r[it] = g_E1[r0 + r];
        b1r[it] = g_B1[r0 + r];
        zacc[it] = 0.f;
    }

    float acc[8][4];
#pragma unroll
    for (int nt = 0; nt < 8; nt++)
#pragma unroll
        for (int e = 0; e < 4; e++) acc[nt][e] = 0.f;

    int2 adjv[4];
#pragma unroll
    for (int it = 0; it < 4; it++)
        adjv[it] = *(const int2*)&adj[(long long)(r0 + it * 16 + rsub) * NN + 2 * kp];

    auto gen = [&](int ti, uint32_t buf) {
        char* phb = sm + PH_OFF + buf * PH_SZ;
        char* plb = sm + PL_OFF + buf * PH_SZ;
        float2 e2 = *(const float2*)&g_E2[ti * 32 + 2 * kp];
        float2 f2 = *(const float2*)&g_F2[ti * 32 + 2 * kp];
#pragma unroll
        for (int it = 0; it < 4; it++) {
            int r = it * 16 + rsub;
            float p0 = adjv[it].x ? fmaxf(e1r[it] * e2.x, b1r[it] * f2.x) : 0.f;
            float p1 = adjv[it].y ? fmaxf(e1r[it] * e2.y, b1r[it] * f2.y) : 0.f;
            zacc[it] += p0 + p1;
            uint32_t hp;
            asm("cvt.rn.bf16x2.f32 %0, %1, %2;" : "=r"(hp) : "f"(p1), "f"(p0));
            float h0f = __uint_as_float(hp << 16);
            float h1f = __uint_as_float(hp & 0xffff0000u);
            uint32_t lp;
            asm("cvt.rn.bf16x2.f32 %0, %1, %2;" : "=r"(lp) : "f"(p1 - h1f), "f"(p0 - h0f));
            *(uint32_t*)(phb + r * 80 + kp * 4) = hp;
            *(uint32_t*)(plb + r * 80 + kp * 4) = lp;
        }
    };
    auto cpWh = [&](int ti, uint32_t buf) {
        const char* src = cpSrcBase + (size_t)ti * 32768;
        uint32_t d = cpDst + buf * WH_SZ;
#pragma unroll
        for (int s4 = 0; s4 < 4; s4++)
            asm volatile("cp.async.cg.shared.global [%0], [%1], 16;"
                         :: "r"(d + s4 * 16), "l"(src + s4 * 16) : "memory");
        asm volatile("cp.async.commit_group;" ::: "memory");
    };

    // ---- prologue
    cpWh(0, 0);
    gen(0, 0);
#pragma unroll
    for (int it = 0; it < 4; it++)
        adjv[it] = *(const int2*)&adj[(long long)(r0 + it * 16 + rsub) * NN + 32 + 2 * kp];

    for (int i = 0; i < 256; i++) {
        uint32_t cur = i & 1, nxt = cur ^ 1;
        asm volatile("cp.async.wait_group 0;" ::: "memory");
        __syncthreads();

        if (i < 255) {
            cpWh(i + 1, nxt);
            gen(i + 1, nxt);
            if (i < 254) {
#pragma unroll
                for (int it = 0; it < 4; it++)
                    adjv[it] = *(const int2*)&adj[(long long)(r0 + it * 16 + rsub) * NN
                                                 + (i + 2) * 32 + 2 * kp];
            }
        }

        // ---- MMA(i)
        uint32_t aH = aAddr + cur * PH_SZ;
        uint32_t aL = aH + 10240u;            // PL_OFF - PH_OFF
        uint32_t bB = bAddr + cur * WH_SZ;
#pragma unroll
        for (int ks = 0; ks < 2; ks++) {
            uint32_t Ah[4], Al[4], Bh[4][4], Bl[4][4];
            ldsm4(Ah, aH + ks * 32);
            ldsm4(Al, aL + ks * 32);
#pragma unroll
            for (int np = 0; np < 4; np++) {
                ldsm4(Bh[np], bB + np * 2304 + ks * 32);
                ldsm4(Bl[np], bB + np * 2304 + ks * 32 + 64);
            }
#pragma unroll
            for (int np = 0; np < 4; np++) {
                mma16816(acc[2*np],   Ah, Bh[np][0], Bh[np][1]);
                mma16816(acc[2*np+1], Ah, Bh[np][2], Bh[np][3]);
            }
#pragma unroll
            for (int np = 0; np < 4; np++) {
                mma16816(acc[2*np],   Al, Bh[np][0], Bh[np][1]);
                mma16816(acc[2*np+1], Al, Bh[np][2], Bh[np][3]);
            }
#pragma unroll
            for (int np = 0; np < 4; np++) {
                mma16816(acc[2*np],   Ah, Bl[np][0], Bl[np][1]);
                mma16816(acc[2*np+1], Ah, Bl[np][2], Bl[np][3]);
            }
        }
    }

    // ---- Z reduce (16 kp lanes per row)
    float* Zs = (float*)(sm + ZS_OFF);
#pragma unroll
    for (int it = 0; it < 4; it++) {
        float z = zacc[it];
        z += __shfl_xor_sync(~0u, z, 1);
        z += __shfl_xor_sync(~0u, z, 2);
        z += __shfl_xor_sync(~0u, z, 4);
        z += __shfl_xor_sync(~0u, z, 8);
        if ((lane & 15) == 0) Zs[it * 16 + rsub] = z;
    }
    __syncthreads();

    // ---- epilogue
    {
        int rl = mb + g;
        float zi0 = __frcp_rn(Zs[rl]);
        float zi1 = __frcp_rn(Zs[rl + 8]);
#pragma unroll
        for (int nt = 0; nt < 8; nt++) {
            int c = cb * 128 + nb + nt * 8 + quad * 2;
            *(float2*)&out[(size_t)(r0 + rl) * FOUT + c] =
                make_float2(acc[nt][0] * zi0, acc[nt][1] * zi0);
            *(float2*)&out[(size_t)(r0 + rl + 8) * FOUT + c] =
                make_float2(acc[nt][2] * zi1, acc[nt][3] * zi1);
        }
    }
}

// ---------------------------------------------------------------------------
extern "C" void kernel_launch(void* const* d_in, const int* in_sizes, int n_in,
                              void* d_out, int out_size) {
    const float* h   = (const float*)d_in[0];
    const int*   adj = (const int*)d_in[1];
    const float* W   = (const float*)d_in[2];
    const float* a   = (const float*)d_in[3];
    float* out = (float*)d_out;

    cudaFuncSetAttribute(k_attn, cudaFuncAttributeMaxDynamicSharedMemorySize, SM_TOT);

    k_wh<<<512, 256>>>(h, W);
    k_tr<<<256, 256>>>();
    k_s12<<<1024, 256>>>(a);
    k_attn<<<256, 256, SM_TOT>>>(adj, out);
}